// round 5
// baseline (speedup 1.0000x reference)
#include <cuda_runtime.h>

#define BB 8
#define NN 4096
#define NPTS (BB*NN)
#define KK 20
#define EPS_BN 1e-5f

// ---- scratch (device globals; no allocation allowed) ----
__device__ float g_xx[NPTS];
__device__ int   g_idx[NPTS*KK];
__device__ float g_x1[NPTS*64];
__device__ float g_x2[NPTS*64];
__device__ float g_x3[NPTS*64];
__device__ float g_cat[(size_t)NPTS*192];
__device__ float g_vf [(size_t)NPTS*1024];
__device__ float g_h7[(size_t)NPTS*512];
__device__ float g_h8[(size_t)NPTS*256];
__device__ float g_gmean[BB*1024];
__device__ float g_part[BB*1024*16];
__device__ float g_b7[BB*512];

// ---- tf32 helpers ----
__device__ __forceinline__ unsigned tf32_of(float a) {
    unsigned r; asm("cvt.rna.tf32.f32 %0, %1;" : "=r"(r) : "f"(a)); return r;
}
__device__ __forceinline__ void mma_tf32(float* c, const unsigned* a, const unsigned* b) {
    asm("mma.sync.aligned.m16n8k8.row.col.f32.tf32.tf32.f32 "
        "{%0,%1,%2,%3}, {%4,%5,%6,%7}, {%8,%9}, {%0,%1,%2,%3};"
        : "+f"(c[0]), "+f"(c[1]), "+f"(c[2]), "+f"(c[3])
        : "r"(a[0]), "r"(a[1]), "r"(a[2]), "r"(a[3]), "r"(b[0]), "r"(b[1]));
}

// ---- xx = sum(x*x, -1) ----
template<int C>
__global__ __launch_bounds__(128) void xx_kernel(const float* __restrict__ x,
                                                 float* __restrict__ xx) {
    int i = blockIdx.x*128 + threadIdx.x;
    float s = 0.f;
    #pragma unroll
    for (int c = 0; c < C; ++c) { float v = x[(size_t)i*C + c]; s = fmaf(v, v, s); }
    xx[i] = s;
}

// ---- kNN: top-20 of pdist = 2*dot - xx_n - xx_m ----
template<int C>
__global__ __launch_bounds__(128) void knn_kernel(const float* __restrict__ x,
                                                  const float* __restrict__ xx,
                                                  int* __restrict__ idxout) {
    constexpr int TILE = 128;
    __shared__ float xs[TILE*C];
    __shared__ float xxs[TILE];
    int tid = threadIdx.x;
    int gpt = blockIdx.x*128 + tid;
    int b = gpt >> 12;
    const float* xb  = x  + (size_t)b*NN*C;
    const float* xxb = xx + (size_t)b*NN;

    float q[C];
    #pragma unroll
    for (int c = 0; c < C; ++c) q[c] = x[(size_t)gpt*C + c];
    float qq = xx[gpt];

    float tv[KK]; int ti[KK];
    #pragma unroll
    for (int s = 0; s < KK; ++s) { tv[s] = -3.4e38f; ti[s] = 0; }

    for (int m0 = 0; m0 < NN; m0 += TILE) {
        __syncthreads();
        for (int l = tid; l < TILE*C; l += 128) xs[l] = xb[(size_t)m0*C + l];
        if (tid < TILE) xxs[tid] = xxb[m0 + tid];
        __syncthreads();
        #pragma unroll 2
        for (int mm = 0; mm < TILE; ++mm) {
            float dot = 0.f;
            if constexpr (C % 4 == 0) {
                const float4* xr = (const float4*)(xs + mm*C);
                #pragma unroll
                for (int c4 = 0; c4 < C/4; ++c4) {
                    float4 v = xr[c4];
                    dot = fmaf(q[4*c4+0], v.x, dot);
                    dot = fmaf(q[4*c4+1], v.y, dot);
                    dot = fmaf(q[4*c4+2], v.z, dot);
                    dot = fmaf(q[4*c4+3], v.w, dot);
                }
            } else {
                #pragma unroll
                for (int c = 0; c < C; ++c) dot = fmaf(q[c], xs[mm*C + c], dot);
            }
            float v = 2.0f*dot - qq - xxs[mm];
            if (v > tv[KK-1]) {
                float cv = v; int ci = m0 + mm;
                #pragma unroll
                for (int s = 0; s < KK; ++s) {
                    if (cv > tv[s]) {
                        float t1 = tv[s]; int t2 = ti[s];
                        tv[s] = cv; ti[s] = ci; cv = t1; ci = t2;
                    }
                }
            }
        }
    }
    #pragma unroll
    for (int s = 0; s < KK; ++s) idxout[(size_t)gpt*KK + s] = ti[s];
}

// ---- fused edge-conv (1 or 2 conv-bn-lrelu) + max over k ----
template<int CIN, bool TWO>
__global__ __launch_bounds__(256) void edgeconv_kernel(
    const float* __restrict__ x, const int* __restrict__ nbr,
    const float* __restrict__ Wa, const float* __restrict__ bna,
    const float* __restrict__ Wb, const float* __restrict__ bnb,
    float* __restrict__ out)
{
    constexpr int C2 = 2*CIN;
    constexpr int GSZ0 = CIN*KK + (TWO ? 64*KK : 0) + CIN + KK;
    constexpr int GSZ  = (GSZ0 + 3) & ~3;
    extern __shared__ float sm[];
    float* Wat  = sm;                         // [C2][64]
    float* Wbt  = Wat + C2*64;                // [64][64] if TWO
    float* bnAs = Wbt + (TWO ? 4096 : 0);
    float* bnBs = bnAs + 192;
    float* grp  = bnBs + (TWO ? 192 : 0);

    int tid = threadIdx.x;
    int g = tid >> 6, o = tid & 63;

    for (int l = tid; l < 64*C2; l += 256) {
        int oo = l / C2, cc = l - oo*C2;
        Wat[cc*64 + oo] = Wa[l];
    }
    if (TWO)
        for (int l = tid; l < 4096; l += 256) Wbt[(l & 63)*64 + (l >> 6)] = Wb[l];
    if (tid < 64) {
        float ga = bna[tid], bt = bna[64+tid], mu = bna[128+tid], va = bna[192+tid];
        bnAs[tid] = ga*rsqrtf(va + EPS_BN); bnAs[64+tid] = mu; bnAs[128+tid] = bt;
    } else if (TWO && tid < 128) {
        int t = tid - 64;
        float ga = bnb[t], bt = bnb[64+t], mu = bnb[128+t], va = bnb[192+t];
        bnBs[t] = ga*rsqrtf(va + EPS_BN); bnBs[64+t] = mu; bnBs[128+t] = bt;
    }
    __syncthreads();

    float* gdiff = grp + g*GSZ;               // [CIN][KK]
    float* gh1   = gdiff + CIN*KK;            // [64][KK] if TWO
    float* gcen  = gh1 + (TWO ? 64*KK : 0);   // [CIN]
    int*   gsnb  = (int*)(gcen + CIN);        // [KK]

    float sA = bnAs[o], mA = bnAs[64+o], bA = bnAs[128+o];
    float sB = 0.f, mB = 0.f, bB = 0.f;
    if (TWO) { sB = bnBs[o]; mB = bnBs[64+o]; bB = bnBs[128+o]; }

    int base = (blockIdx.x*4 + g) * 4;
    for (int p = 0; p < 4; ++p) {
        int gpt = base + p;
        int brow = (gpt >> 12) << 12;
        float cenv = 0.f;
        if (o < CIN) { cenv = x[(size_t)gpt*CIN + o]; gcen[o] = cenv; }
        if (o < KK) gsnb[o] = nbr[(size_t)gpt*KK + o];
        __syncthreads();
        if (o < CIN) {
            #pragma unroll
            for (int j = 0; j < KK; ++j) {
                int m = gsnb[j];
                gdiff[o*KK + j] = x[((size_t)(brow + m))*CIN + o] - cenv;
            }
        }
        float cd = 0.f;
        #pragma unroll
        for (int c = 0; c < CIN; ++c) cd = fmaf(Wat[(CIN + c)*64 + o], gcen[c], cd);
        __syncthreads();

        float acc[KK];
        #pragma unroll
        for (int j = 0; j < KK; ++j) acc[j] = cd;
        #pragma unroll 4
        for (int c = 0; c < CIN; ++c) {
            float w = Wat[c*64 + o];
            const float4* dr = (const float4*)(gdiff + c*KK);
            #pragma unroll
            for (int j4 = 0; j4 < KK/4; ++j4) {
                float4 v = dr[j4];
                acc[4*j4+0] = fmaf(w, v.x, acc[4*j4+0]);
                acc[4*j4+1] = fmaf(w, v.y, acc[4*j4+1]);
                acc[4*j4+2] = fmaf(w, v.z, acc[4*j4+2]);
                acc[4*j4+3] = fmaf(w, v.w, acc[4*j4+3]);
            }
        }
        float vmax = -3.4e38f;
        if (TWO) {
            #pragma unroll
            for (int j = 0; j < KK; ++j) {
                float y = (acc[j] - mA)*sA + bA;
                y = (y >= 0.f) ? y : 0.2f*y;
                gh1[o*KK + j] = y;
            }
            __syncthreads();
            float a2[KK];
            #pragma unroll
            for (int j = 0; j < KK; ++j) a2[j] = 0.f;
            #pragma unroll 4
            for (int c = 0; c < 64; ++c) {
                float w = Wbt[c*64 + o];
                const float4* hr = (const float4*)(gh1 + c*KK);
                #pragma unroll
                for (int j4 = 0; j4 < KK/4; ++j4) {
                    float4 v = hr[j4];
                    a2[4*j4+0] = fmaf(w, v.x, a2[4*j4+0]);
                    a2[4*j4+1] = fmaf(w, v.y, a2[4*j4+1]);
                    a2[4*j4+2] = fmaf(w, v.z, a2[4*j4+2]);
                    a2[4*j4+3] = fmaf(w, v.w, a2[4*j4+3]);
                }
            }
            #pragma unroll
            for (int j = 0; j < KK; ++j) {
                float y = (a2[j] - mB)*sB + bB;
                y = (y >= 0.f) ? y : 0.2f*y;
                vmax = fmaxf(vmax, y);
            }
        } else {
            #pragma unroll
            for (int j = 0; j < KK; ++j) {
                float y = (acc[j] - mA)*sA + bA;
                y = (y >= 0.f) ? y : 0.2f*y;
                vmax = fmaxf(vmax, y);
            }
        }
        out[(size_t)gpt*64 + o] = vmax;
        __syncthreads();
    }
}

// ---- 3xTF32 tensor GEMM: out[m,n] = act(bn(bias[b,n] + sum_k A[m,k]*W[n,k])) ----
// block tile 128(M) x 64(N), K-step 16, 8 warps (4x2), warp tile 32x32
__global__ __launch_bounds__(256) void gemm_tf32_kernel(
    const float* __restrict__ A, int lda,
    const float* __restrict__ W, int ldw,
    const float* __restrict__ bn, const float* __restrict__ bias,
    float* __restrict__ out, int Ncols, int Kd, int act)
{
    __shared__ float Ash[16][132];
    __shared__ float Asl[16][132];
    __shared__ float Wsh[16][68];
    __shared__ float Wsl[16][68];

    int tid = threadIdx.x;
    int lane = tid & 31, warp = tid >> 5;
    int wm = warp >> 1, wn = warp & 1;
    int gid = lane >> 2, tig = lane & 3;

    int bm = blockIdx.y*128, bn0 = blockIdx.x*64;

    float acc[2][4][4];
    #pragma unroll
    for (int mt = 0; mt < 2; ++mt)
        #pragma unroll
        for (int nt = 0; nt < 4; ++nt)
            #pragma unroll
            for (int c = 0; c < 4; ++c) acc[mt][nt][c] = 0.f;

    int arow = tid >> 1, ak = (tid & 1)*8;
    int wrow = tid >> 2, wk = (tid & 3)*4;
    const float* Ap = A + (size_t)(bm + arow)*lda + ak;
    const float* Wp = W + (size_t)(bn0 + wrow)*ldw + wk;

    for (int k0 = 0; k0 < Kd; k0 += 16) {
        float4 av0 = *(const float4*)(Ap + k0);
        float4 av1 = *(const float4*)(Ap + k0 + 4);
        float4 wv  = *(const float4*)(Wp + k0);
        __syncthreads();
        float aval[8] = {av0.x, av0.y, av0.z, av0.w, av1.x, av1.y, av1.z, av1.w};
        #pragma unroll
        for (int j = 0; j < 8; ++j) {
            float hi = __uint_as_float(tf32_of(aval[j]));
            float lo = aval[j] - hi;
            Ash[ak + j][arow] = hi;
            Asl[ak + j][arow] = __uint_as_float(tf32_of(lo));
        }
        float wval[4] = {wv.x, wv.y, wv.z, wv.w};
        #pragma unroll
        for (int j = 0; j < 4; ++j) {
            float hi = __uint_as_float(tf32_of(wval[j]));
            float lo = wval[j] - hi;
            Wsh[wk + j][wrow] = hi;
            Wsl[wk + j][wrow] = __uint_as_float(tf32_of(lo));
        }
        __syncthreads();

        #pragma unroll
        for (int ks = 0; ks < 16; ks += 8) {
            unsigned ah[2][4], al[2][4], bh[4][2], bl[4][2];
            #pragma unroll
            for (int mt = 0; mt < 2; ++mt) {
                int m = wm*32 + mt*16 + gid;
                ah[mt][0] = __float_as_uint(Ash[ks+tig][m]);
                ah[mt][1] = __float_as_uint(Ash[ks+tig][m+8]);
                ah[mt][2] = __float_as_uint(Ash[ks+tig+4][m]);
                ah[mt][3] = __float_as_uint(Ash[ks+tig+4][m+8]);
                al[mt][0] = __float_as_uint(Asl[ks+tig][m]);
                al[mt][1] = __float_as_uint(Asl[ks+tig][m+8]);
                al[mt][2] = __float_as_uint(Asl[ks+tig+4][m]);
                al[mt][3] = __float_as_uint(Asl[ks+tig+4][m+8]);
            }
            #pragma unroll
            for (int nt = 0; nt < 4; ++nt) {
                int n = wn*32 + nt*8 + gid;
                bh[nt][0] = __float_as_uint(Wsh[ks+tig][n]);
                bh[nt][1] = __float_as_uint(Wsh[ks+tig+4][n]);
                bl[nt][0] = __float_as_uint(Wsl[ks+tig][n]);
                bl[nt][1] = __float_as_uint(Wsl[ks+tig+4][n]);
            }
            #pragma unroll
            for (int mt = 0; mt < 2; ++mt)
                #pragma unroll
                for (int nt = 0; nt < 4; ++nt) {
                    mma_tf32(acc[mt][nt], ah[mt], bl[nt]);
                    mma_tf32(acc[mt][nt], al[mt], bh[nt]);
                    mma_tf32(acc[mt][nt], ah[mt], bh[nt]);
                }
        }
    }

    int batch = bm >> 12;
    #pragma unroll
    for (int nt = 0; nt < 4; ++nt) {
        int col0 = bn0 + wn*32 + nt*8 + 2*tig;
        float sc0 = 1.f, mu0 = 0.f, be0 = 0.f, sc1 = 1.f, mu1 = 0.f, be1 = 0.f;
        if (act) {
            float ga0 = bn[col0],   bt0 = bn[Ncols+col0],   m0 = bn[2*Ncols+col0],   va0 = bn[3*Ncols+col0];
            float ga1 = bn[col0+1], bt1 = bn[Ncols+col0+1], m1 = bn[2*Ncols+col0+1], va1 = bn[3*Ncols+col0+1];
            sc0 = ga0*rsqrtf(va0 + EPS_BN); mu0 = m0; be0 = bt0;
            sc1 = ga1*rsqrtf(va1 + EPS_BN); mu1 = m1; be1 = bt1;
        }
        float bv0 = bias ? bias[batch*Ncols + col0]     : 0.f;
        float bv1 = bias ? bias[batch*Ncols + col0 + 1] : 0.f;
        #pragma unroll
        for (int mt = 0; mt < 2; ++mt) {
            int r0 = bm + wm*32 + mt*16 + gid;
            #pragma unroll
            for (int h = 0; h < 2; ++h) {
                int row = r0 + h*8;
                float y0 = acc[mt][nt][2*h]   + bv0;
                float y1 = acc[mt][nt][2*h+1] + bv1;
                if (act) {
                    y0 = (y0 - mu0)*sc0 + be0; y0 = (y0 >= 0.f) ? y0 : 0.2f*y0;
                    y1 = (y1 - mu1)*sc1 + be1; y1 = (y1 >= 0.f) ? y1 : 0.2f*y1;
                }
                float* orow = out + (size_t)row*Ncols + col0;
                orow[0] = y0;
                orow[1] = y1;
            }
        }
    }
}

// ---- concat [x1|x2|x3] -> 192 ----
__global__ __launch_bounds__(256) void concat192_kernel(
    const float* __restrict__ x1, const float* __restrict__ x2,
    const float* __restrict__ x3, float* __restrict__ cat)
{
    int i = blockIdx.x*256 + threadIdx.x;
    int pt = i / 192, c = i - pt*192;
    float v;
    if (c < 64)       v = x1[(size_t)pt*64 + c];
    else if (c < 128) v = x2[(size_t)pt*64 + c - 64];
    else              v = x3[(size_t)pt*64 + c - 128];
    cat[i] = v;
}

// ---- deterministic mean over N (two-pass) ----
__global__ __launch_bounds__(256) void mean1_kernel(const float* __restrict__ vf,
                                                    float* __restrict__ part) {
    int i = blockIdx.x*256 + threadIdx.x;   // B*1024*16
    int c = i & 1023; int t = i >> 10; int b = t >> 4; int s = t & 15;
    const float* p = vf + ((size_t)(b*NN + s*256))*1024 + c;
    float sum = 0.f;
    #pragma unroll 8
    for (int n = 0; n < 256; ++n) sum += p[(size_t)n*1024];
    part[i] = sum;
}

__global__ __launch_bounds__(256) void mean2_kernel(const float* __restrict__ part,
                                                    float* __restrict__ gmean,
                                                    float* __restrict__ outg) {
    int i = blockIdx.x*256 + threadIdx.x;   // B*1024
    int b = i >> 10, c = i & 1023;
    float s = 0.f;
    #pragma unroll
    for (int t = 0; t < 16; ++t) s += part[((b*16 + t) << 10) + c];
    s *= (1.0f/NN);
    gmean[i] = s;
    outg[i] = s;
}

// ---- b7[b,o] = sum_{c<1024} W7[o,c] * g[b,c] ----
__global__ __launch_bounds__(256) void bias7_kernel(const float* __restrict__ gm,
                                                    const float* __restrict__ W7,
                                                    float* __restrict__ b7) {
    int w = (blockIdx.x*256 + threadIdx.x) >> 5;   // 4096 warps: b*512+o
    int lane = threadIdx.x & 31;
    int b = w >> 9, o = w & 511;
    const float* gr = gm + (b << 10);
    const float* wr = W7 + (size_t)o*1216;
    float s = 0.f;
    #pragma unroll 4
    for (int c = lane; c < 1024; c += 32) s = fmaf(wr[c], gr[c], s);
    #pragma unroll
    for (int off = 16; off; off >>= 1) s += __shfl_down_sync(0xffffffffu, s, off);
    if (lane == 0) b7[(b << 9) + o] = s;
}

// ---- final 256 -> 3 projection ----
__global__ __launch_bounds__(256) void final_kernel(const float* __restrict__ h,
                                                    const float* __restrict__ W9,
                                                    float* __restrict__ out) {
    int warp = (blockIdx.x*256 + threadIdx.x) >> 5;
    int lane = threadIdx.x & 31;
    const float* hr = h + (size_t)warp*256;
    float p0 = 0.f, p1 = 0.f, p2 = 0.f;
    #pragma unroll
    for (int c0 = 0; c0 < 256; c0 += 32) {
        int c = c0 + lane;
        float hv = hr[c];
        p0 = fmaf(hv, W9[c],       p0);
        p1 = fmaf(hv, W9[256 + c], p1);
        p2 = fmaf(hv, W9[512 + c], p2);
    }
    #pragma unroll
    for (int off = 16; off; off >>= 1) {
        p0 += __shfl_down_sync(0xffffffffu, p0, off);
        p1 += __shfl_down_sync(0xffffffffu, p1, off);
        p2 += __shfl_down_sync(0xffffffffu, p2, off);
    }
    if (lane == 0) {
        out[(size_t)warp*3 + 0] = p0;
        out[(size_t)warp*3 + 1] = p1;
        out[(size_t)warp*3 + 2] = p2;
    }
}

static int ec_smem(int cin, bool two) {
    int c2 = 2*cin;
    int gsz0 = cin*KK + (two ? 64*KK : 0) + cin + KK;
    int gsz = (gsz0 + 3) & ~3;
    return (c2*64 + (two ? 4096 : 0) + 192 + (two ? 192 : 0) + 4*gsz) * 4;
}

extern "C" void kernel_launch(void* const* d_in, const int* in_sizes, int n_in,
                              void* d_out, int out_size) {
    (void)in_sizes; (void)n_in; (void)out_size;
    const float* x  = (const float*)d_in[0];
    const float* W1 = (const float*)d_in[1];
    const float* W2 = (const float*)d_in[2];
    const float* W3 = (const float*)d_in[3];
    const float* W4 = (const float*)d_in[4];
    const float* W5 = (const float*)d_in[5];
    const float* W6 = (const float*)d_in[6];
    const float* W7 = (const float*)d_in[7];
    const float* W8 = (const float*)d_in[8];
    const float* W9 = (const float*)d_in[9];
    const float* bn1 = (const float*)d_in[10];
    const float* bn2 = (const float*)d_in[11];
    const float* bn3 = (const float*)d_in[12];
    const float* bn4 = (const float*)d_in[13];
    const float* bn5 = (const float*)d_in[14];
    const float* bn6 = (const float*)d_in[15];
    const float* bn7 = (const float*)d_in[16];
    const float* bn8 = (const float*)d_in[17];
    float* outp = (float*)d_out;

    float *xx, *x1, *x2, *x3, *cat, *vf, *h7, *h8, *gmean, *part, *b7;
    int *idx;
    cudaGetSymbolAddress((void**)&xx,  g_xx);
    cudaGetSymbolAddress((void**)&idx, g_idx);
    cudaGetSymbolAddress((void**)&x1,  g_x1);
    cudaGetSymbolAddress((void**)&x2,  g_x2);
    cudaGetSymbolAddress((void**)&x3,  g_x3);
    cudaGetSymbolAddress((void**)&cat, g_cat);
    cudaGetSymbolAddress((void**)&vf,  g_vf);
    cudaGetSymbolAddress((void**)&h7,  g_h7);
    cudaGetSymbolAddress((void**)&h8,  g_h8);
    cudaGetSymbolAddress((void**)&gmean, g_gmean);
    cudaGetSymbolAddress((void**)&part,  g_part);
    cudaGetSymbolAddress((void**)&b7,  g_b7);

    int sm1 = ec_smem(3, true), sm2 = ec_smem(64, true), sm3 = ec_smem(64, false);
    cudaFuncSetAttribute(edgeconv_kernel<3,true>,   cudaFuncAttributeMaxDynamicSharedMemorySize, sm1);
    cudaFuncSetAttribute(edgeconv_kernel<64,true>,  cudaFuncAttributeMaxDynamicSharedMemorySize, sm2);
    cudaFuncSetAttribute(edgeconv_kernel<64,false>, cudaFuncAttributeMaxDynamicSharedMemorySize, sm3);

    // stage 1
    xx_kernel<3><<<NPTS/128, 128>>>(x, xx);
    knn_kernel<3><<<NPTS/128, 128>>>(x, xx, idx);
    edgeconv_kernel<3,true><<<NPTS/16, 256, sm1>>>(x, idx, W1, bn1, W2, bn2, x1);
    // stage 2
    xx_kernel<64><<<NPTS/128, 128>>>(x1, xx);
    knn_kernel<64><<<NPTS/128, 128>>>(x1, xx, idx);
    edgeconv_kernel<64,true><<<NPTS/16, 256, sm2>>>(x1, idx, W3, bn3, W4, bn4, x2);
    // stage 3
    xx_kernel<64><<<NPTS/128, 128>>>(x2, xx);
    knn_kernel<64><<<NPTS/128, 128>>>(x2, xx, idx);
    edgeconv_kernel<64,false><<<NPTS/16, 256, sm3>>>(x2, idx, W5, bn5, nullptr, nullptr, x3);
    // global feature
    concat192_kernel<<<NPTS*192/256, 256>>>(x1, x2, x3, cat);
    gemm_tf32_kernel<<<dim3(1024/64, NPTS/128), 256>>>(cat, 192, W6, 192, bn6, nullptr, vf, 1024, 192, 1);
    mean1_kernel<<<BB*1024*16/256, 256>>>(vf, part);
    mean2_kernel<<<BB*1024/256, 256>>>(part, gmean, outp);          // g -> out[0:8192]
    // decoder: W7·[g;x1;x2;x3] = (W7[:, :1024]·g) + (W7[:,1024:]·cat)
    bias7_kernel<<<512, 256>>>(gmean, W7, b7);
    gemm_tf32_kernel<<<dim3(512/64, NPTS/128), 256>>>(cat, 192, W7 + 1024, 1216, bn7, b7, h7, 512, 192, 1);
    gemm_tf32_kernel<<<dim3(256/64, NPTS/128), 256>>>(h7, 512, W8, 512, bn8, nullptr, h8, 256, 512, 1);
    final_kernel<<<NPTS/8, 256>>>(h8, W9, outp + BB*1024);          // out -> out[8192:]
}